// round 7
// baseline (speedup 1.0000x reference)
#include <cuda_runtime.h>

#define CC 64
#define TT 512
#define VV 25
#define DD 16
#define SS 256
#define NVB 400

#define XP_STR   68
#define KKT_STR  516
#define OFF_KKT  34816
#define OFF_QA   43072
#define OFF_A    47168
#define OFF_KB   55616
#define OFF_RED  55632
#define SMEM_FLOATS 55696      // 222784 bytes

typedef unsigned long long u64;

__device__ __forceinline__ u64 pk2(float a, float b) {
    u64 r; asm("mov.b64 %0, {%1,%2};" : "=l"(r) : "f"(a), "f"(b)); return r;
}
__device__ __forceinline__ u64 f2(u64 a, u64 b, u64 c) {
    u64 d; asm("fma.rn.f32x2 %0, %1, %2, %3;" : "=l"(d) : "l"(a), "l"(b), "l"(c)); return d;
}
__device__ __forceinline__ u64 ad2(u64 a, u64 b) {
    u64 d; asm("add.rn.f32x2 %0, %1, %2;" : "=l"(d) : "l"(a), "l"(b)); return d;
}
__device__ __forceinline__ float2 up2(u64 a) {
    float lo, hi; asm("mov.b64 {%0,%1}, %2;" : "=f"(lo), "=f"(hi) : "l"(a));
    return make_float2(lo, hi);
}

__global__ void __launch_bounds__(512, 1) tgat4_kernel(
    const float* __restrict__ x, const float* __restrict__ W,
    const float* __restrict__ alpha, const float* __restrict__ phi,
    const float* __restrict__ karr, float* __restrict__ out)
{
    extern __shared__ float sm[];
    float* s_xp  = sm;                 // [512][68]
    float* s_kkT = sm + OFF_KKT;       // [16][516]
    float* s_qa  = sm + OFF_QA;        // [256][16]   (= sW during phase 1)
    float* s_A   = sm + OFF_A;         // 8448-float overlay
    float* s_kb  = sm + OFF_KB;        // band kernel
    float* s_red = sm + OFF_RED;       // [16 rows][4 quarters]

    const int tid = threadIdx.x;
    const int nv = blockIdx.x;
    const int n = nv / VV, v = nv - n * VV;

    // ---------- phase 0: W -> smem (qa region), band kernel ----------
    float* sW = s_qa;
    for (int i = tid; i < CC * CC; i += 512) sW[i] = W[i];
    if (tid < 16) s_kb[tid] = (tid < 9) ? karr[tid] : 0.0f;

    // ---------- phase 1: xp = x^T W, 4 chunks of 128 t ----------
    const float* xb = x + ((size_t)n * CC * TT) * VV + v;
    float* xs = s_A;                   // [64][132]
    float xr[16];
    #pragma unroll
    for (int kx = 0; kx < 16; kx++) {
        int idx = tid + kx * 512; int c = idx >> 7, t = idx & 127;
        xr[kx] = __ldg(xb + ((size_t)c * TT + t) * VV);
    }
    const int tg = tid >> 4, dg = tid & 15;
    for (int ch = 0; ch < 4; ch++) {
        if (ch > 0) __syncthreads();
        #pragma unroll
        for (int kx = 0; kx < 16; kx++) {
            int idx = tid + kx * 512; int c = idx >> 7, t = idx & 127;
            xs[c * 132 + t] = xr[kx];
        }
        __syncthreads();
        if (ch < 3) {
            int tb = (ch + 1) * 128;
            #pragma unroll
            for (int kx = 0; kx < 16; kx++) {
                int idx = tid + kx * 512; int c = idx >> 7, t = idx & 127;
                xr[kx] = __ldg(xb + ((size_t)c * TT + tb + t) * VV);
            }
        }
        u64 acc[4][2];
        #pragma unroll
        for (int i = 0; i < 4; i++) { acc[i][0] = pk2(0.f, 0.f); acc[i][1] = acc[i][0]; }
        #pragma unroll 8
        for (int c = 0; c < 64; c++) {
            float4 xv = *(const float4*)(xs + c * 132 + tg * 4);
            ulonglong2 wv = *(const ulonglong2*)(sW + c * 64 + dg * 4);
            u64 x0 = pk2(xv.x, xv.x), x1 = pk2(xv.y, xv.y);
            u64 x2 = pk2(xv.z, xv.z), x3 = pk2(xv.w, xv.w);
            acc[0][0] = f2(x0, wv.x, acc[0][0]); acc[0][1] = f2(x0, wv.y, acc[0][1]);
            acc[1][0] = f2(x1, wv.x, acc[1][0]); acc[1][1] = f2(x1, wv.y, acc[1][1]);
            acc[2][0] = f2(x2, wv.x, acc[2][0]); acc[2][1] = f2(x2, wv.y, acc[2][1]);
            acc[3][0] = f2(x3, wv.x, acc[3][0]); acc[3][1] = f2(x3, wv.y, acc[3][1]);
        }
        #pragma unroll
        for (int i = 0; i < 4; i++) {
            ulonglong2 st; st.x = acc[i][0]; st.y = acc[i][1];
            *(ulonglong2*)(s_xp + (size_t)(ch * 128 + tg * 4 + i) * XP_STR + dg * 4) = st;
        }
    }
    __syncthreads();

    // ---------- phase 2: kkT = (xp@phi)^T ; q = (xp@alpha)/16 ----------
    float* sAl = s_A;                  // [64][16]
    float* sPh = s_A + 1024;           // [64][16]
    for (int i = tid; i < 1024; i += 512) { sAl[i] = alpha[i] * 0.0625f; sPh[i] = phi[i]; }
    __syncthreads();
    {
        const int w = tid >> 5, l = tid & 31;
        const int t2 = (w & 7) * 64 + l * 2 + (w >> 3);
        const bool doq = (w < 8);
        u64 kacc[8], qacc[8];
        #pragma unroll
        for (int j = 0; j < 8; j++) { kacc[j] = pk2(0.f, 0.f); qacc[j] = kacc[j]; }
        #pragma unroll 4
        for (int c4 = 0; c4 < 16; c4++) {
            float4 xv = *(const float4*)(s_xp + (size_t)t2 * XP_STR + c4 * 4);
            float xe[4] = {xv.x, xv.y, xv.z, xv.w};
            #pragma unroll
            for (int e = 0; e < 4; e++) {
                int c = c4 * 4 + e;
                u64 xd = pk2(xe[e], xe[e]);
                const ulonglong2* pp = (const ulonglong2*)(sPh + c * 16);
                ulonglong2 p0 = pp[0], p1 = pp[1], p2 = pp[2], p3 = pp[3];
                kacc[0] = f2(xd, p0.x, kacc[0]); kacc[1] = f2(xd, p0.y, kacc[1]);
                kacc[2] = f2(xd, p1.x, kacc[2]); kacc[3] = f2(xd, p1.y, kacc[3]);
                kacc[4] = f2(xd, p2.x, kacc[4]); kacc[5] = f2(xd, p2.y, kacc[5]);
                kacc[6] = f2(xd, p3.x, kacc[6]); kacc[7] = f2(xd, p3.y, kacc[7]);
                if (doq) {
                    const ulonglong2* aa = (const ulonglong2*)(sAl + c * 16);
                    ulonglong2 a0 = aa[0], a1 = aa[1], a2 = aa[2], a3 = aa[3];
                    qacc[0] = f2(xd, a0.x, qacc[0]); qacc[1] = f2(xd, a0.y, qacc[1]);
                    qacc[2] = f2(xd, a1.x, qacc[2]); qacc[3] = f2(xd, a1.y, qacc[3]);
                    qacc[4] = f2(xd, a2.x, qacc[4]); qacc[5] = f2(xd, a2.y, qacc[5]);
                    qacc[6] = f2(xd, a3.x, qacc[6]); qacc[7] = f2(xd, a3.y, qacc[7]);
                }
            }
        }
        #pragma unroll
        for (int j = 0; j < 8; j++) {
            float2 kv = up2(kacc[j]);
            s_kkT[(2 * j) * KKT_STR + t2]     = kv.x;
            s_kkT[(2 * j + 1) * KKT_STR + t2] = kv.y;
        }
        if (doq) {
            int s = t2 >> 1;
            u64* qrow = (u64*)(s_qa + s * 16);
            #pragma unroll
            for (int j = 0; j < 8; j++) qrow[j] = qacc[j];
        }
    }
    __syncthreads();

    // ---------- phase 3: 16 tiles of 16 s-rows ----------
    const int w = tid >> 5, l = tid & 31;
    const int rg = w & 3;              // row group: rows rg*4..+3
    const int qt = w >> 2;             // t quarter
    const int dgrp = tid & 15, chunk = (tid >> 4) & 15, sblk = tid >> 8;
    float* s_att = s_A;                // [16][516]
    float* s_p4  = s_A;                // partials (after att dead)

    const float* kbase = s_kkT + qt * 128 + l * 4;

    for (int tile = 0; tile < 16; tile++) {
        const int s0 = tile * 16;

        // ---- scores: rows rg*4..+3, t = qt*128 + l*4 .. +3 ----
        u64 ac[4][2];
        #pragma unroll
        for (int r = 0; r < 4; r++) { ac[r][0] = pk2(0.f, 0.f); ac[r][1] = ac[r][0]; }
        #pragma unroll
        for (int j4 = 0; j4 < 4; j4++) {
            float4 q0 = *(const float4*)(s_qa + (s0 + rg * 4 + 0) * 16 + j4 * 4);
            float4 q1 = *(const float4*)(s_qa + (s0 + rg * 4 + 1) * 16 + j4 * 4);
            float4 q2 = *(const float4*)(s_qa + (s0 + rg * 4 + 2) * 16 + j4 * 4);
            float4 q3 = *(const float4*)(s_qa + (s0 + rg * 4 + 3) * 16 + j4 * 4);
            #pragma unroll
            for (int jj = 0; jj < 4; jj++) {
                ulonglong2 kv = *(const ulonglong2*)(kbase + (j4 * 4 + jj) * KKT_STR);
                float q0e = jj == 0 ? q0.x : jj == 1 ? q0.y : jj == 2 ? q0.z : q0.w;
                float q1e = jj == 0 ? q1.x : jj == 1 ? q1.y : jj == 2 ? q1.z : q1.w;
                float q2e = jj == 0 ? q2.x : jj == 1 ? q2.y : jj == 2 ? q2.z : q2.w;
                float q3e = jj == 0 ? q3.x : jj == 1 ? q3.y : jj == 2 ? q3.z : q3.w;
                u64 d0 = pk2(q0e, q0e), d1 = pk2(q1e, q1e);
                u64 d2 = pk2(q2e, q2e), d3 = pk2(q3e, q3e);
                ac[0][0] = f2(d0, kv.x, ac[0][0]); ac[0][1] = f2(d0, kv.y, ac[0][1]);
                ac[1][0] = f2(d1, kv.x, ac[1][0]); ac[1][1] = f2(d1, kv.y, ac[1][1]);
                ac[2][0] = f2(d2, kv.x, ac[2][0]); ac[2][1] = f2(d2, kv.y, ac[2][1]);
                ac[3][0] = f2(d3, kv.x, ac[3][0]); ac[3][1] = f2(d3, kv.y, ac[3][1]);
            }
        }

        // ---- exp (no max-sub: |score| << 1) + row sums ----
        float e[4][4];
        float rs[4];
        #pragma unroll
        for (int r = 0; r < 4; r++) {
            float2 lo = up2(ac[r][0]), hi = up2(ac[r][1]);
            e[r][0] = __expf(lo.x); e[r][1] = __expf(lo.y);
            e[r][2] = __expf(hi.x); e[r][3] = __expf(hi.y);
            rs[r] = (e[r][0] + e[r][1]) + (e[r][2] + e[r][3]);
            #pragma unroll
            for (int o = 16; o > 0; o >>= 1)
                rs[r] += __shfl_xor_sync(0xffffffffu, rs[r], o);
        }
        if (l == 0) {
            #pragma unroll
            for (int r = 0; r < 4; r++) s_red[(rg * 4 + r) * 4 + qt] = rs[r];
        }
        __syncthreads();

        // ---- normalize + band prior + store att ----
        #pragma unroll
        for (int r = 0; r < 4; r++) {
            int row = rg * 4 + r;
            float4 rv = *(const float4*)(s_red + row * 4);
            float inv = 1.0f / ((rv.x + rv.y) + (rv.z + rv.w));
            int tb = qt * 128 + l * 4;
            int tr = 2 * (s0 + row);
            float4 ev;
            ev.x = e[r][0] * inv; ev.y = e[r][1] * inv;
            ev.z = e[r][2] * inv; ev.w = e[r][3] * inv;
            int o;
            o = tb + 0 - tr + 4; if ((unsigned)o < 9u) ev.x += s_kb[o];
            o = tb + 1 - tr + 4; if ((unsigned)o < 9u) ev.y += s_kb[o];
            o = tb + 2 - tr + 4; if ((unsigned)o < 9u) ev.z += s_kb[o];
            o = tb + 3 - tr + 4; if ((unsigned)o < 9u) ev.w += s_kb[o];
            *(float4*)(s_att + row * KKT_STR + tb) = ev;
        }
        __syncthreads();

        // ---- out tile: 8 s-rows x 4 d per thread, 16-way t split ----
        u64 oc[8][2];
        #pragma unroll
        for (int r = 0; r < 8; r++) { oc[r][0] = pk2(0.f, 0.f); oc[r][1] = oc[r][0]; }
        #pragma unroll 2
        for (int it = 0; it < 8; it++) {
            int f4i = it * 16 + chunk;
            const float* xpb = s_xp + (size_t)f4i * 4 * XP_STR + dgrp * 4;
            ulonglong2 xv0 = *(const ulonglong2*)(xpb);
            ulonglong2 xv1 = *(const ulonglong2*)(xpb + XP_STR);
            ulonglong2 xv2 = *(const ulonglong2*)(xpb + 2 * XP_STR);
            ulonglong2 xv3 = *(const ulonglong2*)(xpb + 3 * XP_STR);
            #pragma unroll
            for (int r = 0; r < 8; r++) {
                float4 av = *(const float4*)(s_att + (sblk * 8 + r) * KKT_STR + f4i * 4);
                u64 d0 = pk2(av.x, av.x), d1 = pk2(av.y, av.y);
                u64 d2 = pk2(av.z, av.z), d3 = pk2(av.w, av.w);
                oc[r][0] = f2(d0, xv0.x, oc[r][0]); oc[r][1] = f2(d0, xv0.y, oc[r][1]);
                oc[r][0] = f2(d1, xv1.x, oc[r][0]); oc[r][1] = f2(d1, xv1.y, oc[r][1]);
                oc[r][0] = f2(d2, xv2.x, oc[r][0]); oc[r][1] = f2(d2, xv2.y, oc[r][1]);
                oc[r][0] = f2(d3, xv3.x, oc[r][0]); oc[r][1] = f2(d3, xv3.y, oc[r][1]);
            }
        }
        __syncthreads();                              // att reads done

        // ---- 3-stage partial reduction (cc-major layout) ----
        if (chunk >= 8) {
            int cc = chunk - 8;
            #pragma unroll
            for (int r = 0; r < 8; r++) {
                int o4 = (sblk * 8 + r) * 16 + dgrp;
                ulonglong2 st; st.x = oc[r][0]; st.y = oc[r][1];
                *(ulonglong2*)(s_p4 + (cc * 256 + o4) * 4) = st;
            }
        }
        __syncthreads();
        if (chunk < 8) {
            #pragma unroll
            for (int r = 0; r < 8; r++) {
                int o4 = (sblk * 8 + r) * 16 + dgrp;
                ulonglong2 pv = *(const ulonglong2*)(s_p4 + (chunk * 256 + o4) * 4);
                oc[r][0] = ad2(oc[r][0], pv.x);
                oc[r][1] = ad2(oc[r][1], pv.y);
                ulonglong2 st; st.x = oc[r][0]; st.y = oc[r][1];
                *(ulonglong2*)(s_p4 + (chunk * 256 + o4) * 4) = st;
            }
        }
        __syncthreads();
        if (tid < 256) {
            const float* pb = s_p4 + tid * 4;
            u64 s0u = pk2(0.f, 0.f), s1u = s0u;
            #pragma unroll
            for (int cc = 0; cc < 8; cc++) {
                ulonglong2 pv = *(const ulonglong2*)(pb + cc * 1024);
                s0u = ad2(s0u, pv.x); s1u = ad2(s1u, pv.y);
            }
            float2 f01 = up2(s0u), f23 = up2(s1u);
            int row = tid >> 4, dq = tid & 15;
            int sidx = s0 + row;
            size_t ob = (((size_t)n * CC + dq * 4) * SS + sidx) * VV + v;
            const size_t dst = (size_t)SS * VV;
            out[ob] = f01.x; out[ob + dst] = f01.y;
            out[ob + 2 * dst] = f23.x; out[ob + 3 * dst] = f23.y;
        }
        // no final barrier: stage-3 p4 reads are ordered against next tile's
        // att writes by the next tile's sum-exchange __syncthreads()
    }
}

extern "C" void kernel_launch(void* const* d_in, const int* in_sizes, int n_in,
                              void* d_out, int out_size)
{
    const float* x     = (const float*)d_in[0];
    const float* W     = (const float*)d_in[1];
    const float* alpha = (const float*)d_in[2];
    const float* phi   = (const float*)d_in[3];
    const float* karr  = (const float*)d_in[4];
    float* out = (float*)d_out;

    const int smemB = SMEM_FLOATS * sizeof(float);   // 222784 bytes
    cudaFuncSetAttribute(tgat4_kernel,
                         cudaFuncAttributeMaxDynamicSharedMemorySize, smemB);
    tgat4_kernel<<<NVB, 512, smemB>>>(x, W, alpha, phi, karr, out);
}

// round 8
// speedup vs baseline: 1.0158x; 1.0158x over previous
#include <cuda_runtime.h>

#define CC 64
#define TT 512
#define VV 25
#define DD 16
#define SS 256
#define NVB 400

#define XP_STR   68
#define KKT_STR  516
#define OFF_KKT  34816
#define OFF_QA   43072
#define OFF_A    47168
#define OFF_KB   55616
#define OFF_RED  55632
#define SMEM_FLOATS 55696      // 222784 bytes

typedef unsigned long long u64;

__device__ __forceinline__ u64 pk2(float a, float b) {
    u64 r; asm("mov.b64 %0, {%1,%2};" : "=l"(r) : "f"(a), "f"(b)); return r;
}
__device__ __forceinline__ u64 f2(u64 a, u64 b, u64 c) {
    u64 d; asm("fma.rn.f32x2 %0, %1, %2, %3;" : "=l"(d) : "l"(a), "l"(b), "l"(c)); return d;
}
__device__ __forceinline__ u64 ad2(u64 a, u64 b) {
    u64 d; asm("add.rn.f32x2 %0, %1, %2;" : "=l"(d) : "l"(a), "l"(b)); return d;
}
__device__ __forceinline__ float2 up2(u64 a) {
    float lo, hi; asm("mov.b64 {%0,%1}, %2;" : "=f"(lo), "=f"(hi) : "l"(a));
    return make_float2(lo, hi);
}

__global__ void __launch_bounds__(512, 1) tgat4_kernel(
    const float* __restrict__ x, const float* __restrict__ W,
    const float* __restrict__ alpha, const float* __restrict__ phi,
    const float* __restrict__ karr, float* __restrict__ out)
{
    extern __shared__ float sm[];
    float* s_xp  = sm;                 // [512][68]
    float* s_kkT = sm + OFF_KKT;       // [16][516]
    float* s_qa  = sm + OFF_QA;        // [256][16]   (= sW during phase 1)
    float* s_A   = sm + OFF_A;         // 8448-float overlay
    float* s_kb  = sm + OFF_KB;        // band kernel
    float* s_red = sm + OFF_RED;       // [16 rows][4 quarters]

    const int tid = threadIdx.x;
    const int nv = blockIdx.x;
    const int n = nv / VV, v = nv - n * VV;

    // ---------- phase 0: W -> smem (qa region), band kernel ----------
    float* sW = s_qa;
    for (int i = tid; i < CC * CC; i += 512) sW[i] = W[i];
    if (tid < 16) s_kb[tid] = (tid < 9) ? karr[tid] : 0.0f;

    // ---------- phase 1: xp = x^T W, 4 chunks of 128 t ----------
    const float* xb = x + ((size_t)n * CC * TT) * VV + v;
    float* xs = s_A;                   // [64][132]
    float xr[16];
    #pragma unroll
    for (int kx = 0; kx < 16; kx++) {
        int idx = tid + kx * 512; int c = idx >> 7, t = idx & 127;
        xr[kx] = __ldg(xb + ((size_t)c * TT + t) * VV);
    }
    const int tg = tid >> 4, dg = tid & 15;
    for (int ch = 0; ch < 4; ch++) {
        if (ch > 0) __syncthreads();
        #pragma unroll
        for (int kx = 0; kx < 16; kx++) {
            int idx = tid + kx * 512; int c = idx >> 7, t = idx & 127;
            xs[c * 132 + t] = xr[kx];
        }
        __syncthreads();
        if (ch < 3) {
            int tb = (ch + 1) * 128;
            #pragma unroll
            for (int kx = 0; kx < 16; kx++) {
                int idx = tid + kx * 512; int c = idx >> 7, t = idx & 127;
                xr[kx] = __ldg(xb + ((size_t)c * TT + tb + t) * VV);
            }
        }
        u64 acc[4][2];
        #pragma unroll
        for (int i = 0; i < 4; i++) { acc[i][0] = pk2(0.f, 0.f); acc[i][1] = acc[i][0]; }
        #pragma unroll 8
        for (int c = 0; c < 64; c++) {
            float4 xv = *(const float4*)(xs + c * 132 + tg * 4);
            ulonglong2 wv = *(const ulonglong2*)(sW + c * 64 + dg * 4);
            u64 x0 = pk2(xv.x, xv.x), x1 = pk2(xv.y, xv.y);
            u64 x2 = pk2(xv.z, xv.z), x3 = pk2(xv.w, xv.w);
            acc[0][0] = f2(x0, wv.x, acc[0][0]); acc[0][1] = f2(x0, wv.y, acc[0][1]);
            acc[1][0] = f2(x1, wv.x, acc[1][0]); acc[1][1] = f2(x1, wv.y, acc[1][1]);
            acc[2][0] = f2(x2, wv.x, acc[2][0]); acc[2][1] = f2(x2, wv.y, acc[2][1]);
            acc[3][0] = f2(x3, wv.x, acc[3][0]); acc[3][1] = f2(x3, wv.y, acc[3][1]);
        }
        #pragma unroll
        for (int i = 0; i < 4; i++) {
            ulonglong2 st; st.x = acc[i][0]; st.y = acc[i][1];
            *(ulonglong2*)(s_xp + (size_t)(ch * 128 + tg * 4 + i) * XP_STR + dg * 4) = st;
        }
    }
    __syncthreads();

    // ---------- phase 2: kkT = (xp@phi)^T ; q = (xp@alpha)/16 ----------
    float* sAl = s_A;                  // [64][16]
    float* sPh = s_A + 1024;           // [64][16]
    for (int i = tid; i < 1024; i += 512) { sAl[i] = alpha[i] * 0.0625f; sPh[i] = phi[i]; }
    __syncthreads();
    {
        const int w = tid >> 5, l = tid & 31;
        const int t2 = (w & 7) * 64 + l * 2 + (w >> 3);
        const bool doq = (w < 8);
        u64 kacc[8], qacc[8];
        #pragma unroll
        for (int j = 0; j < 8; j++) { kacc[j] = pk2(0.f, 0.f); qacc[j] = kacc[j]; }
        #pragma unroll 4
        for (int c4 = 0; c4 < 16; c4++) {
            float4 xv = *(const float4*)(s_xp + (size_t)t2 * XP_STR + c4 * 4);
            float xe[4] = {xv.x, xv.y, xv.z, xv.w};
            #pragma unroll
            for (int e = 0; e < 4; e++) {
                int c = c4 * 4 + e;
                u64 xd = pk2(xe[e], xe[e]);
                const ulonglong2* pp = (const ulonglong2*)(sPh + c * 16);
                ulonglong2 p0 = pp[0], p1 = pp[1], p2 = pp[2], p3 = pp[3];
                kacc[0] = f2(xd, p0.x, kacc[0]); kacc[1] = f2(xd, p0.y, kacc[1]);
                kacc[2] = f2(xd, p1.x, kacc[2]); kacc[3] = f2(xd, p1.y, kacc[3]);
                kacc[4] = f2(xd, p2.x, kacc[4]); kacc[5] = f2(xd, p2.y, kacc[5]);
                kacc[6] = f2(xd, p3.x, kacc[6]); kacc[7] = f2(xd, p3.y, kacc[7]);
                if (doq) {
                    const ulonglong2* aa = (const ulonglong2*)(sAl + c * 16);
                    ulonglong2 a0 = aa[0], a1 = aa[1], a2 = aa[2], a3 = aa[3];
                    qacc[0] = f2(xd, a0.x, qacc[0]); qacc[1] = f2(xd, a0.y, qacc[1]);
                    qacc[2] = f2(xd, a1.x, qacc[2]); qacc[3] = f2(xd, a1.y, qacc[3]);
                    qacc[4] = f2(xd, a2.x, qacc[4]); qacc[5] = f2(xd, a2.y, qacc[5]);
                    qacc[6] = f2(xd, a3.x, qacc[6]); qacc[7] = f2(xd, a3.y, qacc[7]);
                }
            }
        }
        #pragma unroll
        for (int j = 0; j < 8; j++) {
            float2 kv = up2(kacc[j]);
            s_kkT[(2 * j) * KKT_STR + t2]     = kv.x;
            s_kkT[(2 * j + 1) * KKT_STR + t2] = kv.y;
        }
        if (doq) {
            int s = t2 >> 1;
            u64* qrow = (u64*)(s_qa + s * 16);
            #pragma unroll
            for (int j = 0; j < 8; j++) qrow[j] = qacc[j];
        }
    }
    __syncthreads();

    // ---------- phase 3: 16 tiles of 16 s-rows ----------
    const int w = tid >> 5, l = tid & 31;
    const int rg = w & 3;              // row group: rows rg*4..+3
    const int qt = w >> 2;             // t quarter
    const int dgrp = tid & 15, chunk = (tid >> 4) & 15, sblk = tid >> 8;
    float* s_att = s_A;                // [16][516]
    float* s_p4  = s_A;                // partials (after att dead)

    const float* kbase = s_kkT + qt * 128 + l * 4;

    for (int tile = 0; tile < 16; tile++) {
        const int s0 = tile * 16;

        // ---- scores: rows rg*4..+3, t = qt*128 + l*4 .. +3 ----
        u64 ac[4][2];
        #pragma unroll
        for (int r = 0; r < 4; r++) { ac[r][0] = pk2(0.f, 0.f); ac[r][1] = ac[r][0]; }
        #pragma unroll
        for (int j4 = 0; j4 < 4; j4++) {
            float4 q0 = *(const float4*)(s_qa + (s0 + rg * 4 + 0) * 16 + j4 * 4);
            float4 q1 = *(const float4*)(s_qa + (s0 + rg * 4 + 1) * 16 + j4 * 4);
            float4 q2 = *(const float4*)(s_qa + (s0 + rg * 4 + 2) * 16 + j4 * 4);
            float4 q3 = *(const float4*)(s_qa + (s0 + rg * 4 + 3) * 16 + j4 * 4);
            #pragma unroll
            for (int jj = 0; jj < 4; jj++) {
                ulonglong2 kv = *(const ulonglong2*)(kbase + (j4 * 4 + jj) * KKT_STR);
                float q0e = jj == 0 ? q0.x : jj == 1 ? q0.y : jj == 2 ? q0.z : q0.w;
                float q1e = jj == 0 ? q1.x : jj == 1 ? q1.y : jj == 2 ? q1.z : q1.w;
                float q2e = jj == 0 ? q2.x : jj == 1 ? q2.y : jj == 2 ? q2.z : q2.w;
                float q3e = jj == 0 ? q3.x : jj == 1 ? q3.y : jj == 2 ? q3.z : q3.w;
                u64 d0 = pk2(q0e, q0e), d1 = pk2(q1e, q1e);
                u64 d2 = pk2(q2e, q2e), d3 = pk2(q3e, q3e);
                ac[0][0] = f2(d0, kv.x, ac[0][0]); ac[0][1] = f2(d0, kv.y, ac[0][1]);
                ac[1][0] = f2(d1, kv.x, ac[1][0]); ac[1][1] = f2(d1, kv.y, ac[1][1]);
                ac[2][0] = f2(d2, kv.x, ac[2][0]); ac[2][1] = f2(d2, kv.y, ac[2][1]);
                ac[3][0] = f2(d3, kv.x, ac[3][0]); ac[3][1] = f2(d3, kv.y, ac[3][1]);
            }
        }

        // ---- exp (no max-sub: |score| << 1) + row sums ----
        float e[4][4];
        float rs[4];
        #pragma unroll
        for (int r = 0; r < 4; r++) {
            float2 lo = up2(ac[r][0]), hi = up2(ac[r][1]);
            e[r][0] = __expf(lo.x); e[r][1] = __expf(lo.y);
            e[r][2] = __expf(hi.x); e[r][3] = __expf(hi.y);
            rs[r] = (e[r][0] + e[r][1]) + (e[r][2] + e[r][3]);
            #pragma unroll
            for (int o = 16; o > 0; o >>= 1)
                rs[r] += __shfl_xor_sync(0xffffffffu, rs[r], o);
        }
        if (l == 0) {
            #pragma unroll
            for (int r = 0; r < 4; r++) s_red[(rg * 4 + r) * 4 + qt] = rs[r];
        }
        __syncthreads();

        // ---- normalize + band prior + store att ----
        #pragma unroll
        for (int r = 0; r < 4; r++) {
            int row = rg * 4 + r;
            float4 rv = *(const float4*)(s_red + row * 4);
            float inv = 1.0f / ((rv.x + rv.y) + (rv.z + rv.w));
            int tb = qt * 128 + l * 4;
            int tr = 2 * (s0 + row);
            float4 ev;
            ev.x = e[r][0] * inv; ev.y = e[r][1] * inv;
            ev.z = e[r][2] * inv; ev.w = e[r][3] * inv;
            int o;
            o = tb + 0 - tr + 4; if ((unsigned)o < 9u) ev.x += s_kb[o];
            o = tb + 1 - tr + 4; if ((unsigned)o < 9u) ev.y += s_kb[o];
            o = tb + 2 - tr + 4; if ((unsigned)o < 9u) ev.z += s_kb[o];
            o = tb + 3 - tr + 4; if ((unsigned)o < 9u) ev.w += s_kb[o];
            *(float4*)(s_att + row * KKT_STR + tb) = ev;
        }
        __syncthreads();

        // ---- out tile: 8 s-rows x 4 d per thread, 16-way t split ----
        u64 oc[8][2];
        #pragma unroll
        for (int r = 0; r < 8; r++) { oc[r][0] = pk2(0.f, 0.f); oc[r][1] = oc[r][0]; }
        #pragma unroll 2
        for (int it = 0; it < 8; it++) {
            int f4i = it * 16 + chunk;
            const float* xpb = s_xp + (size_t)f4i * 4 * XP_STR + dgrp * 4;
            ulonglong2 xv0 = *(const ulonglong2*)(xpb);
            ulonglong2 xv1 = *(const ulonglong2*)(xpb + XP_STR);
            ulonglong2 xv2 = *(const ulonglong2*)(xpb + 2 * XP_STR);
            ulonglong2 xv3 = *(const ulonglong2*)(xpb + 3 * XP_STR);
            #pragma unroll
            for (int r = 0; r < 8; r++) {
                float4 av = *(const float4*)(s_att + (sblk * 8 + r) * KKT_STR + f4i * 4);
                u64 d0 = pk2(av.x, av.x), d1 = pk2(av.y, av.y);
                u64 d2 = pk2(av.z, av.z), d3 = pk2(av.w, av.w);
                oc[r][0] = f2(d0, xv0.x, oc[r][0]); oc[r][1] = f2(d0, xv0.y, oc[r][1]);
                oc[r][0] = f2(d1, xv1.x, oc[r][0]); oc[r][1] = f2(d1, xv1.y, oc[r][1]);
                oc[r][0] = f2(d2, xv2.x, oc[r][0]); oc[r][1] = f2(d2, xv2.y, oc[r][1]);
                oc[r][0] = f2(d3, xv3.x, oc[r][0]); oc[r][1] = f2(d3, xv3.y, oc[r][1]);
            }
        }
        __syncthreads();                              // att reads done

        // ---- 3-stage partial reduction (cc-major layout) ----
        if (chunk >= 8) {
            int cc = chunk - 8;
            #pragma unroll
            for (int r = 0; r < 8; r++) {
                int o4 = (sblk * 8 + r) * 16 + dgrp;
                ulonglong2 st; st.x = oc[r][0]; st.y = oc[r][1];
                *(ulonglong2*)(s_p4 + (cc * 256 + o4) * 4) = st;
            }
        }
        __syncthreads();
        if (chunk < 8) {
            #pragma unroll
            for (int r = 0; r < 8; r++) {
                int o4 = (sblk * 8 + r) * 16 + dgrp;
                ulonglong2 pv = *(const ulonglong2*)(s_p4 + (chunk * 256 + o4) * 4);
                oc[r][0] = ad2(oc[r][0], pv.x);
                oc[r][1] = ad2(oc[r][1], pv.y);
                ulonglong2 st; st.x = oc[r][0]; st.y = oc[r][1];
                *(ulonglong2*)(s_p4 + (chunk * 256 + o4) * 4) = st;
            }
        }
        __syncthreads();
        if (tid < 256) {
            const float* pb = s_p4 + tid * 4;
            u64 s0u = pk2(0.f, 0.f), s1u = s0u;
            #pragma unroll
            for (int cc = 0; cc < 8; cc++) {
                ulonglong2 pv = *(const ulonglong2*)(pb + cc * 1024);
                s0u = ad2(s0u, pv.x); s1u = ad2(s1u, pv.y);
            }
            float2 f01 = up2(s0u), f23 = up2(s1u);
            int row = tid >> 4, dq = tid & 15;
            int sidx = s0 + row;
            size_t ob = (((size_t)n * CC + dq * 4) * SS + sidx) * VV + v;
            const size_t dst = (size_t)SS * VV;
            out[ob] = f01.x; out[ob + dst] = f01.y;
            out[ob + 2 * dst] = f23.x; out[ob + 3 * dst] = f23.y;
        }
        // no final barrier: stage-3 p4 reads are ordered against next tile's
        // att writes by the next tile's sum-exchange __syncthreads()
    }
}

extern "C" void kernel_launch(void* const* d_in, const int* in_sizes, int n_in,
                              void* d_out, int out_size)
{
    const float* x     = (const float*)d_in[0];
    const float* W     = (const float*)d_in[1];
    const float* alpha = (const float*)d_in[2];
    const float* phi   = (const float*)d_in[3];
    const float* karr  = (const float*)d_in[4];
    float* out = (float*)d_out;

    const int smemB = SMEM_FLOATS * sizeof(float);   // 222784 bytes
    cudaFuncSetAttribute(tgat4_kernel,
                         cudaFuncAttributeMaxDynamicSharedMemorySize, smemB);
    tgat4_kernel<<<NVB, 512, smemB>>>(x, W, alpha, phi, karr, out);
}

// round 9
// speedup vs baseline: 1.0775x; 1.0608x over previous
#include <cuda_runtime.h>

#define CC 64
#define TT 512
#define VV 25
#define DD 16
#define SS 256
#define NVB 400

#define XP_STR   68
#define KKT_STR  516
#define OFF_KKT  34816
#define OFF_QA   43072
#define OFF_A    47168
#define OFF_KB   55616
#define OFF_RED  55632
#define SMEM_FLOATS 55696      // 222784 bytes

typedef unsigned long long u64;

__device__ __forceinline__ u64 pk2(float a, float b) {
    u64 r; asm("mov.b64 %0, {%1,%2};" : "=l"(r) : "f"(a), "f"(b)); return r;
}
__device__ __forceinline__ u64 f2(u64 a, u64 b, u64 c) {
    u64 d; asm("fma.rn.f32x2 %0, %1, %2, %3;" : "=l"(d) : "l"(a), "l"(b), "l"(c)); return d;
}
__device__ __forceinline__ u64 ad2(u64 a, u64 b) {
    u64 d; asm("add.rn.f32x2 %0, %1, %2;" : "=l"(d) : "l"(a), "l"(b)); return d;
}
__device__ __forceinline__ float2 up2(u64 a) {
    float lo, hi; asm("mov.b64 {%0,%1}, %2;" : "=f"(lo), "=f"(hi) : "l"(a));
    return make_float2(lo, hi);
}

__global__ void __launch_bounds__(512, 1) tgat5_kernel(
    const float* __restrict__ x, const float* __restrict__ W,
    const float* __restrict__ alpha, const float* __restrict__ phi,
    const float* __restrict__ karr, float* __restrict__ out)
{
    extern __shared__ float sm[];
    float* s_xp  = sm;                 // [512][68]
    float* s_kkT = sm + OFF_KKT;       // [16][516]
    float* s_qa  = sm + OFF_QA;        // [256][16]   (= sW during phase 1)
    float* s_A   = sm + OFF_A;         // 8448-float overlay
    float* s_kb  = sm + OFF_KB;        // band kernel
    float* s_red = sm + OFF_RED;       // [16 rows][4 quarters]

    const int tid = threadIdx.x;
    const int nv = blockIdx.x;
    const int n = nv / VV, v = nv - n * VV;

    // ---------- phase 0: W -> smem (qa region), band kernel ----------
    float* sW = s_qa;
    for (int i = tid; i < CC * CC; i += 512) sW[i] = W[i];
    if (tid < 16) s_kb[tid] = (tid < 9) ? karr[tid] : 0.0f;

    // ---------- phase 1: xp = x^T W, 4 chunks of 128 t ----------
    const float* xb = x + ((size_t)n * CC * TT) * VV + v;
    float* xs = s_A;                   // [64][132]
    float xr[16];
    #pragma unroll
    for (int kx = 0; kx < 16; kx++) {
        int idx = tid + kx * 512; int c = idx >> 7, t = idx & 127;
        xr[kx] = __ldg(xb + ((size_t)c * TT + t) * VV);
    }
    const int tg = tid >> 4, dg = tid & 15;
    for (int ch = 0; ch < 4; ch++) {
        if (ch > 0) __syncthreads();
        #pragma unroll
        for (int kx = 0; kx < 16; kx++) {
            int idx = tid + kx * 512; int c = idx >> 7, t = idx & 127;
            xs[c * 132 + t] = xr[kx];
        }
        __syncthreads();
        if (ch < 3) {
            int tb = (ch + 1) * 128;
            #pragma unroll
            for (int kx = 0; kx < 16; kx++) {
                int idx = tid + kx * 512; int c = idx >> 7, t = idx & 127;
                xr[kx] = __ldg(xb + ((size_t)c * TT + tb + t) * VV);
            }
        }
        u64 acc[4][2];
        #pragma unroll
        for (int i = 0; i < 4; i++) { acc[i][0] = pk2(0.f, 0.f); acc[i][1] = acc[i][0]; }
        #pragma unroll 8
        for (int c = 0; c < 64; c++) {
            float4 xv = *(const float4*)(xs + c * 132 + tg * 4);
            ulonglong2 wv = *(const ulonglong2*)(sW + c * 64 + dg * 4);
            u64 x0 = pk2(xv.x, xv.x), x1 = pk2(xv.y, xv.y);
            u64 x2 = pk2(xv.z, xv.z), x3 = pk2(xv.w, xv.w);
            acc[0][0] = f2(x0, wv.x, acc[0][0]); acc[0][1] = f2(x0, wv.y, acc[0][1]);
            acc[1][0] = f2(x1, wv.x, acc[1][0]); acc[1][1] = f2(x1, wv.y, acc[1][1]);
            acc[2][0] = f2(x2, wv.x, acc[2][0]); acc[2][1] = f2(x2, wv.y, acc[2][1]);
            acc[3][0] = f2(x3, wv.x, acc[3][0]); acc[3][1] = f2(x3, wv.y, acc[3][1]);
        }
        #pragma unroll
        for (int i = 0; i < 4; i++) {
            ulonglong2 st; st.x = acc[i][0]; st.y = acc[i][1];
            *(ulonglong2*)(s_xp + (size_t)(ch * 128 + tg * 4 + i) * XP_STR + dg * 4) = st;
        }
    }
    __syncthreads();

    // ---------- phase 2: kkT = (xp@phi)^T ; q = (xp@alpha)/16 ----------
    float* sAl = s_A;                  // [64][16]
    float* sPh = s_A + 1024;           // [64][16]
    for (int i = tid; i < 1024; i += 512) { sAl[i] = alpha[i] * 0.0625f; sPh[i] = phi[i]; }
    __syncthreads();
    {
        const int w = tid >> 5, l = tid & 31;
        const int t2 = (w & 7) * 64 + l * 2 + (w >> 3);
        const bool doq = (w < 8);
        u64 kacc[8], qacc[8];
        #pragma unroll
        for (int j = 0; j < 8; j++) { kacc[j] = pk2(0.f, 0.f); qacc[j] = kacc[j]; }
        #pragma unroll 4
        for (int c4 = 0; c4 < 16; c4++) {
            float4 xv = *(const float4*)(s_xp + (size_t)t2 * XP_STR + c4 * 4);
            float xe[4] = {xv.x, xv.y, xv.z, xv.w};
            #pragma unroll
            for (int e = 0; e < 4; e++) {
                int c = c4 * 4 + e;
                u64 xd = pk2(xe[e], xe[e]);
                const ulonglong2* pp = (const ulonglong2*)(sPh + c * 16);
                ulonglong2 p0 = pp[0], p1 = pp[1], p2 = pp[2], p3 = pp[3];
                kacc[0] = f2(xd, p0.x, kacc[0]); kacc[1] = f2(xd, p0.y, kacc[1]);
                kacc[2] = f2(xd, p1.x, kacc[2]); kacc[3] = f2(xd, p1.y, kacc[3]);
                kacc[4] = f2(xd, p2.x, kacc[4]); kacc[5] = f2(xd, p2.y, kacc[5]);
                kacc[6] = f2(xd, p3.x, kacc[6]); kacc[7] = f2(xd, p3.y, kacc[7]);
                if (doq) {
                    const ulonglong2* aa = (const ulonglong2*)(sAl + c * 16);
                    ulonglong2 a0 = aa[0], a1 = aa[1], a2 = aa[2], a3 = aa[3];
                    qacc[0] = f2(xd, a0.x, qacc[0]); qacc[1] = f2(xd, a0.y, qacc[1]);
                    qacc[2] = f2(xd, a1.x, qacc[2]); qacc[3] = f2(xd, a1.y, qacc[3]);
                    qacc[4] = f2(xd, a2.x, qacc[4]); qacc[5] = f2(xd, a2.y, qacc[5]);
                    qacc[6] = f2(xd, a3.x, qacc[6]); qacc[7] = f2(xd, a3.y, qacc[7]);
                }
            }
        }
        #pragma unroll
        for (int j = 0; j < 8; j++) {
            float2 kv = up2(kacc[j]);
            s_kkT[(2 * j) * KKT_STR + t2]     = kv.x;
            s_kkT[(2 * j + 1) * KKT_STR + t2] = kv.y;
        }
        if (doq) {
            int s = t2 >> 1;
            u64* qrow = (u64*)(s_qa + s * 16);
            #pragma unroll
            for (int j = 0; j < 8; j++) qrow[j] = qacc[j];
        }
    }
    __syncthreads();

    // ---------- phase 3: 16 tiles of 16 s-rows ----------
    const int w = tid >> 5, l = tid & 31;
    const int rg = w & 3;              // scores: row group rg*4..+3
    const int qt = w >> 2;             // scores: t quarter
    const int rblk = (w & 1) * 8;      // gemm: s-rows rblk..+7
    const int dblk = (w >> 1) * 8;     // gemm: d cols dblk..+7
    float* s_att = s_A;                // [16][516]

    const float* kbase = s_kkT + qt * 128 + l * 4;
    const float* attb  = s_att + rblk * KKT_STR + l;
    const float* xpb   = s_xp + (size_t)l * XP_STR + dblk;
    const size_t dstg  = (size_t)SS * VV;

    for (int tile = 0; tile < 16; tile++) {
        const int s0 = tile * 16;

        // ---- scores: rows rg*4..+3, t = qt*128 + l*4 .. +3 ----
        u64 ac[4][2];
        #pragma unroll
        for (int r = 0; r < 4; r++) { ac[r][0] = pk2(0.f, 0.f); ac[r][1] = ac[r][0]; }
        #pragma unroll
        for (int j4 = 0; j4 < 4; j4++) {
            float4 q0 = *(const float4*)(s_qa + (s0 + rg * 4 + 0) * 16 + j4 * 4);
            float4 q1 = *(const float4*)(s_qa + (s0 + rg * 4 + 1) * 16 + j4 * 4);
            float4 q2 = *(const float4*)(s_qa + (s0 + rg * 4 + 2) * 16 + j4 * 4);
            float4 q3 = *(const float4*)(s_qa + (s0 + rg * 4 + 3) * 16 + j4 * 4);
            #pragma unroll
            for (int jj = 0; jj < 4; jj++) {
                ulonglong2 kv = *(const ulonglong2*)(kbase + (j4 * 4 + jj) * KKT_STR);
                float q0e = jj == 0 ? q0.x : jj == 1 ? q0.y : jj == 2 ? q0.z : q0.w;
                float q1e = jj == 0 ? q1.x : jj == 1 ? q1.y : jj == 2 ? q1.z : q1.w;
                float q2e = jj == 0 ? q2.x : jj == 1 ? q2.y : jj == 2 ? q2.z : q2.w;
                float q3e = jj == 0 ? q3.x : jj == 1 ? q3.y : jj == 2 ? q3.z : q3.w;
                u64 d0 = pk2(q0e, q0e), d1 = pk2(q1e, q1e);
                u64 d2 = pk2(q2e, q2e), d3 = pk2(q3e, q3e);
                ac[0][0] = f2(d0, kv.x, ac[0][0]); ac[0][1] = f2(d0, kv.y, ac[0][1]);
                ac[1][0] = f2(d1, kv.x, ac[1][0]); ac[1][1] = f2(d1, kv.y, ac[1][1]);
                ac[2][0] = f2(d2, kv.x, ac[2][0]); ac[2][1] = f2(d2, kv.y, ac[2][1]);
                ac[3][0] = f2(d3, kv.x, ac[3][0]); ac[3][1] = f2(d3, kv.y, ac[3][1]);
            }
        }

        // ---- exp (no max-sub: |score| << 1) + row sums ----
        float e[4][4];
        float rs[4];
        #pragma unroll
        for (int r = 0; r < 4; r++) {
            float2 lo = up2(ac[r][0]), hi = up2(ac[r][1]);
            e[r][0] = __expf(lo.x); e[r][1] = __expf(lo.y);
            e[r][2] = __expf(hi.x); e[r][3] = __expf(hi.y);
            rs[r] = (e[r][0] + e[r][1]) + (e[r][2] + e[r][3]);
            #pragma unroll
            for (int o = 16; o > 0; o >>= 1)
                rs[r] += __shfl_xor_sync(0xffffffffu, rs[r], o);
        }
        if (l == 0) {
            #pragma unroll
            for (int r = 0; r < 4; r++) s_red[(rg * 4 + r) * 4 + qt] = rs[r];
        }
        __syncthreads();                               // bar 1: sums ready

        // ---- normalize + band prior + store att ----
        #pragma unroll
        for (int r = 0; r < 4; r++) {
            int row = rg * 4 + r;
            float4 rv = *(const float4*)(s_red + row * 4);
            float inv = 1.0f / ((rv.x + rv.y) + (rv.z + rv.w));
            int tb = qt * 128 + l * 4;
            int tr = 2 * (s0 + row);
            float4 ev;
            ev.x = e[r][0] * inv; ev.y = e[r][1] * inv;
            ev.z = e[r][2] * inv; ev.w = e[r][3] * inv;
            int o;
            o = tb + 0 - tr + 4; if ((unsigned)o < 9u) ev.x += s_kb[o];
            o = tb + 1 - tr + 4; if ((unsigned)o < 9u) ev.y += s_kb[o];
            o = tb + 2 - tr + 4; if ((unsigned)o < 9u) ev.z += s_kb[o];
            o = tb + 3 - tr + 4; if ((unsigned)o < 9u) ev.w += s_kb[o];
            *(float4*)(s_att + row * KKT_STR + tb) = ev;
        }
        __syncthreads();                               // bar 2: att ready

        // ---- out GEMM: warp owns 8s x 8d block; lane = t-slice ----
        u64 A[32];                                     // m = r*4 + dpair
        #pragma unroll
        for (int m = 0; m < 32; m++) A[m] = pk2(0.f, 0.f);
        #pragma unroll 4
        for (int i = 0; i < 16; i++) {
            const float* xq = xpb + (size_t)(i * 32) * XP_STR;
            ulonglong2 xv0 = *(const ulonglong2*)(xq);
            ulonglong2 xv1 = *(const ulonglong2*)(xq + 4);
            const float* aq = attb + i * 32;
            #pragma unroll
            for (int r = 0; r < 8; r++) {
                float a = aq[r * KKT_STR];
                u64 ad = pk2(a, a);
                A[r*4+0] = f2(ad, xv0.x, A[r*4+0]);
                A[r*4+1] = f2(ad, xv0.y, A[r*4+1]);
                A[r*4+2] = f2(ad, xv1.x, A[r*4+2]);
                A[r*4+3] = f2(ad, xv1.y, A[r*4+3]);
            }
        }

        // ---- butterfly reduce: lane ends with element m = lane ----
        #pragma unroll
        for (int o = 16; o >= 1; o >>= 1) {
            bool hi = (l & o) != 0;
            #pragma unroll
            for (int j = 0; j < 16; j++) {
                if (j < o) {
                    u64 send = hi ? A[j] : A[j + o];
                    u64 keep = hi ? A[j + o] : A[j];
                    u64 got = __shfl_xor_sync(0xffffffffu, send, o);
                    A[j] = ad2(keep, got);
                }
            }
        }
        {
            float2 res = up2(A[0]);
            int r = l >> 2, dp = l & 3;
            int sidx = s0 + rblk + r;
            size_t ob = (((size_t)n * CC + dblk + dp * 2) * SS + sidx) * VV + v;
            out[ob] = res.x;
            out[ob + dstg] = res.y;
        }
        // no bar: next tile's att writes are ordered behind its own bar 1,
        // which this tile's GEMM reads precede in program order.
    }
}

extern "C" void kernel_launch(void* const* d_in, const int* in_sizes, int n_in,
                              void* d_out, int out_size)
{
    const float* x     = (const float*)d_in[0];
    const float* W     = (const float*)d_in[1];
    const float* alpha = (const float*)d_in[2];
    const float* phi   = (const float*)d_in[3];
    const float* karr  = (const float*)d_in[4];
    float* out = (float*)d_out;

    const int smemB = SMEM_FLOATS * sizeof(float);   // 222784 bytes
    cudaFuncSetAttribute(tgat5_kernel,
                         cudaFuncAttributeMaxDynamicSharedMemorySize, smemB);
    tgat5_kernel<<<NVB, 512, smemB>>>(x, W, alpha, phi, karr, out);
}